// round 12
// baseline (speedup 1.0000x reference)
#include <cuda_runtime.h>

// GarNet aggregation: out[b, s*64+n] = (sum_v w[v,s]) * (sum_v w[v,s]*fi[v,n]) / (128*128)
// with w = exp(-d_av^2).  B=4096, V=128, S=16, N=64.
//
// R12: one-warp CTAs. fi goes DIRECTLY to registers via a 16-deep LDG.128
// rotation (no smem round-trip; dependency distance ~840 cyc > DRAM latency).
// Only d streams through smem (cp.async, 4 stages x 1KB), w computed in place.
static constexpr int Bc = 4096;
static constexpr int Vc = 128;
static constexpr int Sc = 16;
static constexpr int Nc = 64;
static constexpr int VCH = 16;       // v per chunk (= fi rotation depth)
static constexpr int NCH = Vc / VCH; // 8 chunks
static constexpr int NST = 4;        // d/w pipeline stages

// Smem (floats): d/w 4 stages x (16*16), w in place over d
static constexpr int SBUF = NST * VCH * Sc;   // 1024 floats = 4096 B

typedef unsigned long long u64;

__device__ __forceinline__ u64 bcast2(float x) {
    u64 r; unsigned xi = __float_as_uint(x);
    asm("mov.b64 %0, {%1, %1};" : "=l"(r) : "r"(xi));
    return r;
}
__device__ __forceinline__ void ffma2(u64 &c, u64 a, u64 b) {
    asm("fma.rn.f32x2 %0, %1, %2, %0;" : "+l"(c) : "l"(a), "l"(b));
}
__device__ __forceinline__ float lo32(u64 v) { return __uint_as_float((unsigned)(v & 0xffffffffull)); }
__device__ __forceinline__ float hi32(u64 v) { return __uint_as_float((unsigned)(v >> 32)); }

__device__ __forceinline__ void cp16(unsigned saddr, const void* gaddr) {
    asm volatile("cp.async.cg.shared.global [%0], [%1], 16;" :: "r"(saddr), "l"(gaddr));
}
__device__ __forceinline__ void cp_commit() {
    asm volatile("cp.async.commit_group;" ::: "memory");
}
template <int N>
__device__ __forceinline__ void cp_wait() {
    asm volatile("cp.async.wait_group %0;" :: "n"(N) : "memory");
}

__global__ __launch_bounds__(32)
void garnet_kernel(const float* __restrict__ fi,
                   const float* __restrict__ dav,
                   float* __restrict__ out) {
    __shared__ __align__(16) float s_dw[SBUF];
    __shared__ float s_wbar[Sc];

    const int lane = threadIdx.x & 31;
    const int ng   = lane & 15;   // n-group: owns n = ng*4 .. ng*4+3
    const int sh   = lane >> 4;   // s-half:  owns s = sh*8 .. sh*8+7
    const long b   = (long)blockIdx.x;

    unsigned sw = (unsigned)__cvta_generic_to_shared(s_dw);
    const float4* __restrict__ fsrc = (const float4*)(fi + b * (long)(Vc * Nc)) + ng;
    const float*  __restrict__ d_g  = dav + b * (long)(Vc * Sc);

    // ---- issue d chunk c into stage c%4: 2 cp16 per lane --------------------
    auto issue = [&](int c) {
        int st = c & (NST - 1);
        unsigned ddst = sw + (st * (VCH * Sc)) * 4 + lane * 16;
        const float* dsrc = d_g + c * (VCH * Sc) + lane * 4;
        #pragma unroll
        for (int i = 0; i < 2; i++)
            cp16(ddst + i * 512, dsrc + i * 128);
        cp_commit();
    };

    u64 acc[16];   // acc[sp*4+j]: lo = s=sh*8+2sp, hi = s+1, n = ng*4+j
    #pragma unroll
    for (int i = 0; i < 16; i++) acc[i] = 0ull;
    float wb0 = 0.f, wb1 = 0.f, wb2 = 0.f, wb3 = 0.f;  // col partials, s=(lane&3)*4+k

    issue(0); issue(1); issue(2);

    // ---- fi rotation prologue: 16 outstanding LDG.128 -----------------------
    float4 fbuf[VCH];
    #pragma unroll
    for (int i = 0; i < VCH; i++)
        fbuf[i] = fsrc[i * (Nc / 4)];

    for (int c = 0; c < NCH; c++) {
        if (c + 3 < NCH)      { issue(c + 3); cp_wait<3>(); }
        else if (c + 2 < NCH) { cp_wait<2>(); }
        else if (c + 1 < NCH) { cp_wait<1>(); }
        else                  { cp_wait<0>(); }
        __syncwarp();

        const int st = c & (NST - 1);
        // ---- w = exp(-d^2), IN PLACE over the d stage ----------------------
        float4* dwbuf = (float4*)(s_dw + st * (VCH * Sc));
        #pragma unroll
        for (int j = 0; j < 2; j++) {
            int idx = j * 32 + lane;          // 0..63 float4s
            float4 d4 = dwbuf[idx];
            float4 w4;
            w4.x = __expf(-d4.x * d4.x);
            w4.y = __expf(-d4.y * d4.y);
            w4.z = __expf(-d4.z * d4.z);
            w4.w = __expf(-d4.w * d4.w);
            dwbuf[idx] = w4;
            wb0 += w4.x; wb1 += w4.y; wb2 += w4.z; wb3 += w4.w;
        }
        __syncwarp();

        // ---- FFMA2 over the 16 v of this chunk; fi from registers ----------
        const float* wf   = s_dw + st * (VCH * Sc) + sh * 8;
        const bool   more = (c + 1 < NCH);
        #pragma unroll
        for (int vv = 0; vv < VCH; vv++) {
            float4 f4 = fbuf[vv];
            if (more)   // loop-invariant predicate: refill slot with v+16
                fbuf[vv] = fsrc[((c + 1) * VCH + vv) * (Nc / 4)];
            const ulonglong2* wp = (const ulonglong2*)(wf + vv * Sc);
            ulonglong2 wA = wp[0], wB = wp[1];
            u64 w0 = wA.x, w1 = wA.y, w2 = wB.x, w3 = wB.y;
            u64 f0 = bcast2(f4.x), f1 = bcast2(f4.y);
            u64 f2 = bcast2(f4.z), f3 = bcast2(f4.w);
            ffma2(acc[ 0], w0, f0); ffma2(acc[ 1], w0, f1);
            ffma2(acc[ 2], w0, f2); ffma2(acc[ 3], w0, f3);
            ffma2(acc[ 4], w1, f0); ffma2(acc[ 5], w1, f1);
            ffma2(acc[ 6], w1, f2); ffma2(acc[ 7], w1, f3);
            ffma2(acc[ 8], w2, f0); ffma2(acc[ 9], w2, f1);
            ffma2(acc[10], w2, f2); ffma2(acc[11], w2, f3);
            ffma2(acc[12], w3, f0); ffma2(acc[13], w3, f1);
            ffma2(acc[14], w3, f2); ffma2(acc[15], w3, f3);
        }
        __syncwarp();   // w stage reused by cp.async four chunks later
    }

    // ---- wbar: reduce col partials over lanes of same class (lane&3) --------
    wb0 += __shfl_xor_sync(0xffffffffu, wb0, 16);
    wb0 += __shfl_xor_sync(0xffffffffu, wb0, 8);
    wb0 += __shfl_xor_sync(0xffffffffu, wb0, 4);
    wb1 += __shfl_xor_sync(0xffffffffu, wb1, 16);
    wb1 += __shfl_xor_sync(0xffffffffu, wb1, 8);
    wb1 += __shfl_xor_sync(0xffffffffu, wb1, 4);
    wb2 += __shfl_xor_sync(0xffffffffu, wb2, 16);
    wb2 += __shfl_xor_sync(0xffffffffu, wb2, 8);
    wb2 += __shfl_xor_sync(0xffffffffu, wb2, 4);
    wb3 += __shfl_xor_sync(0xffffffffu, wb3, 16);
    wb3 += __shfl_xor_sync(0xffffffffu, wb3, 8);
    wb3 += __shfl_xor_sync(0xffffffffu, wb3, 4);
    if (lane < 4) {
        s_wbar[lane * 4 + 0] = wb0;
        s_wbar[lane * 4 + 1] = wb1;
        s_wbar[lane * 4 + 2] = wb2;
        s_wbar[lane * 4 + 3] = wb3;
    }
    __syncwarp();

    // ---- epilogue: out = wbar * acc / (V*V) ---------------------------------
    const float inv = 1.0f / 16384.0f;
    float* obase = out + b * (long)(Sc * Nc) + ng * 4;
    #pragma unroll
    for (int sp = 0; sp < 4; sp++) {
        int s0 = sh * 8 + 2 * sp;
        float se = s_wbar[s0]     * inv;
        float so = s_wbar[s0 + 1] * inv;
        float4 oe, oo;
        oe.x = lo32(acc[sp * 4 + 0]) * se;
        oe.y = lo32(acc[sp * 4 + 1]) * se;
        oe.z = lo32(acc[sp * 4 + 2]) * se;
        oe.w = lo32(acc[sp * 4 + 3]) * se;
        oo.x = hi32(acc[sp * 4 + 0]) * so;
        oo.y = hi32(acc[sp * 4 + 1]) * so;
        oo.z = hi32(acc[sp * 4 + 2]) * so;
        oo.w = hi32(acc[sp * 4 + 3]) * so;
        *(float4*)(obase + s0 * Nc)       = oe;
        *(float4*)(obase + (s0 + 1) * Nc) = oo;
    }
}

extern "C" void kernel_launch(void* const* d_in, const int* in_sizes, int n_in,
                              void* d_out, int out_size) {
    const float* fi  = (const float*)d_in[0];
    const float* dav = (const float*)d_in[1];
    // Defensive: identify by element count (d_av has 4096*128*16 elems)
    if (n_in >= 2 && in_sizes[0] == Bc * Vc * Sc) {
        const float* tmp = fi; fi = dav; dav = tmp;
    }
    garnet_kernel<<<Bc, 32>>>(fi, dav, (float*)d_out);
}

// round 13
// speedup vs baseline: 1.0639x; 1.0639x over previous
#include <cuda_runtime.h>

// GarNet aggregation: out[b, s*64+n] = (sum_v w[v,s]) * (sum_v w[v,s]*fi[v,n]) / (128*128)
// with w = exp(-d_av^2).  B=4096, V=128, S=16, N=64.
//
// R13: one-warp CTAs, VCH=8, 5-STAGE cp.async pipeline with cp_wait<4>:
// small stages (2KB fi) -> 12.8KB/CTA -> ~16 CTAs/SM, while keeping ~1700cyc
// of latency slack. w computed in place over the d stage.
static constexpr int Bc = 4096;
static constexpr int Vc = 128;
static constexpr int Sc = 16;
static constexpr int Nc = 64;
static constexpr int VCH = 8;        // v per chunk
static constexpr int NCH = Vc / VCH; // 16 chunks
static constexpr int NST = 5;        // pipeline stages

// Smem (floats): fi 5 stages x (8*64) | d/w 5 stages x (8*16), w in place
static constexpr int OFF_FI = 0;                  // 5*512 floats
static constexpr int OFF_D  = NST * VCH * Nc;     // 2560; 5*128 floats
static constexpr int SBUF   = OFF_D + NST * VCH * Sc;   // 3200 floats = 12800 B

typedef unsigned long long u64;

__device__ __forceinline__ u64 bcast2(float x) {
    u64 r; unsigned xi = __float_as_uint(x);
    asm("mov.b64 %0, {%1, %1};" : "=l"(r) : "r"(xi));
    return r;
}
__device__ __forceinline__ void ffma2(u64 &c, u64 a, u64 b) {
    asm("fma.rn.f32x2 %0, %1, %2, %0;" : "+l"(c) : "l"(a), "l"(b));
}
__device__ __forceinline__ float lo32(u64 v) { return __uint_as_float((unsigned)(v & 0xffffffffull)); }
__device__ __forceinline__ float hi32(u64 v) { return __uint_as_float((unsigned)(v >> 32)); }

__device__ __forceinline__ void cp16(unsigned saddr, const void* gaddr) {
    asm volatile("cp.async.cg.shared.global [%0], [%1], 16;" :: "r"(saddr), "l"(gaddr));
}
__device__ __forceinline__ void cp_commit() {
    asm volatile("cp.async.commit_group;" ::: "memory");
}
template <int N>
__device__ __forceinline__ void cp_wait() {
    asm volatile("cp.async.wait_group %0;" :: "n"(N) : "memory");
}

__global__ __launch_bounds__(32)
void garnet_kernel(const float* __restrict__ fi,
                   const float* __restrict__ dav,
                   float* __restrict__ out) {
    __shared__ __align__(16) float s_buf[SBUF];
    __shared__ float s_wbar[Sc];

    const int lane = threadIdx.x & 31;
    const int ng   = lane & 15;   // n-group: owns n = ng*4 .. ng*4+3
    const int sh   = lane >> 4;   // s-half:  owns s = sh*8 .. sh*8+7
    const long b   = (long)blockIdx.x;

    unsigned sw = (unsigned)__cvta_generic_to_shared(s_buf);
    const float* fi_g = fi  + b * (long)(Vc * Nc);
    const float* d_g  = dav + b * (long)(Vc * Sc);

    // ---- issue chunk c into stage c%5: 4 fi cp16 + 1 d cp16 per lane --------
    auto issue = [&](int c) {
        int st = c % NST;
        unsigned fidst = sw + (OFF_FI + st * (VCH * Nc)) * 4 + lane * 16;
        const float* fisrc = fi_g + c * (VCH * Nc) + lane * 4;
        #pragma unroll
        for (int i = 0; i < 4; i++)
            cp16(fidst + i * 512, fisrc + i * 128);
        unsigned ddst = sw + (OFF_D + st * (VCH * Sc)) * 4 + lane * 16;
        const float* dsrc = d_g + c * (VCH * Sc) + lane * 4;
        cp16(ddst, dsrc);
        cp_commit();
    };

    u64 acc[16];   // acc[sp*4+j]: lo = s=sh*8+2sp, hi = s+1, n = ng*4+j
    #pragma unroll
    for (int i = 0; i < 16; i++) acc[i] = 0ull;
    float wb0 = 0.f, wb1 = 0.f, wb2 = 0.f, wb3 = 0.f;  // col partials, s=(lane&3)*4+k

    issue(0); issue(1); issue(2); issue(3);

    #pragma unroll 5
    for (int c = 0; c < NCH; c++) {
        if (c + 4 < NCH)      { issue(c + 4); cp_wait<4>(); }
        else if (c + 3 < NCH) { cp_wait<3>(); }
        else if (c + 2 < NCH) { cp_wait<2>(); }
        else if (c + 1 < NCH) { cp_wait<1>(); }
        else                  { cp_wait<0>(); }
        __syncwarp();

        const int st = c % NST;
        // ---- w = exp(-d^2), IN PLACE over the d stage (32 float4s) ---------
        float4* dwbuf = (float4*)(s_buf + OFF_D + st * (VCH * Sc));
        {
            float4 d4 = dwbuf[lane];
            float4 w4;
            w4.x = __expf(-d4.x * d4.x);
            w4.y = __expf(-d4.y * d4.y);
            w4.z = __expf(-d4.z * d4.z);
            w4.w = __expf(-d4.w * d4.w);
            dwbuf[lane] = w4;
            wb0 += w4.x; wb1 += w4.y; wb2 += w4.z; wb3 += w4.w;
        }
        __syncwarp();

        // ---- FFMA2 over the 8 v of this chunk (all smem) -------------------
        const float4* fibuf = (const float4*)(s_buf + OFF_FI + st * (VCH * Nc));
        const float*  wf    = s_buf + OFF_D + st * (VCH * Sc) + sh * 8;
        #pragma unroll
        for (int vv = 0; vv < VCH; vv++) {
            float4 f4 = fibuf[vv * (Nc / 4) + ng];
            const ulonglong2* wp = (const ulonglong2*)(wf + vv * Sc);
            ulonglong2 wA = wp[0], wB = wp[1];
            u64 w0 = wA.x, w1 = wA.y, w2 = wB.x, w3 = wB.y;
            u64 f0 = bcast2(f4.x), f1 = bcast2(f4.y);
            u64 f2 = bcast2(f4.z), f3 = bcast2(f4.w);
            ffma2(acc[ 0], w0, f0); ffma2(acc[ 1], w0, f1);
            ffma2(acc[ 2], w0, f2); ffma2(acc[ 3], w0, f3);
            ffma2(acc[ 4], w1, f0); ffma2(acc[ 5], w1, f1);
            ffma2(acc[ 6], w1, f2); ffma2(acc[ 7], w1, f3);
            ffma2(acc[ 8], w2, f0); ffma2(acc[ 9], w2, f1);
            ffma2(acc[10], w2, f2); ffma2(acc[11], w2, f3);
            ffma2(acc[12], w3, f0); ffma2(acc[13], w3, f1);
            ffma2(acc[14], w3, f2); ffma2(acc[15], w3, f3);
        }
        __syncwarp();   // stage is reused by cp.async five chunks later
    }

    // ---- wbar: reduce col partials over lanes of same class (lane&3) --------
    wb0 += __shfl_xor_sync(0xffffffffu, wb0, 16);
    wb0 += __shfl_xor_sync(0xffffffffu, wb0, 8);
    wb0 += __shfl_xor_sync(0xffffffffu, wb0, 4);
    wb1 += __shfl_xor_sync(0xffffffffu, wb1, 16);
    wb1 += __shfl_xor_sync(0xffffffffu, wb1, 8);
    wb1 += __shfl_xor_sync(0xffffffffu, wb1, 4);
    wb2 += __shfl_xor_sync(0xffffffffu, wb2, 16);
    wb2 += __shfl_xor_sync(0xffffffffu, wb2, 8);
    wb2 += __shfl_xor_sync(0xffffffffu, wb2, 4);
    wb3 += __shfl_xor_sync(0xffffffffu, wb3, 16);
    wb3 += __shfl_xor_sync(0xffffffffu, wb3, 8);
    wb3 += __shfl_xor_sync(0xffffffffu, wb3, 4);
    if (lane < 4) {
        s_wbar[lane * 4 + 0] = wb0;
        s_wbar[lane * 4 + 1] = wb1;
        s_wbar[lane * 4 + 2] = wb2;
        s_wbar[lane * 4 + 3] = wb3;
    }
    __syncwarp();

    // ---- epilogue: out = wbar * acc / (V*V) ---------------------------------
    const float inv = 1.0f / 16384.0f;
    float* obase = out + b * (long)(Sc * Nc) + ng * 4;
    #pragma unroll
    for (int sp = 0; sp < 4; sp++) {
        int s0 = sh * 8 + 2 * sp;
        float se = s_wbar[s0]     * inv;
        float so = s_wbar[s0 + 1] * inv;
        float4 oe, oo;
        oe.x = lo32(acc[sp * 4 + 0]) * se;
        oe.y = lo32(acc[sp * 4 + 1]) * se;
        oe.z = lo32(acc[sp * 4 + 2]) * se;
        oe.w = lo32(acc[sp * 4 + 3]) * se;
        oo.x = hi32(acc[sp * 4 + 0]) * so;
        oo.y = hi32(acc[sp * 4 + 1]) * so;
        oo.z = hi32(acc[sp * 4 + 2]) * so;
        oo.w = hi32(acc[sp * 4 + 3]) * so;
        *(float4*)(obase + s0 * Nc)       = oe;
        *(float4*)(obase + (s0 + 1) * Nc) = oo;
    }
}

extern "C" void kernel_launch(void* const* d_in, const int* in_sizes, int n_in,
                              void* d_out, int out_size) {
    const float* fi  = (const float*)d_in[0];
    const float* dav = (const float*)d_in[1];
    // Defensive: identify by element count (d_av has 4096*128*16 elems)
    if (n_in >= 2 && in_sizes[0] == Bc * Vc * Sc) {
        const float* tmp = fi; fi = dav; dav = tmp;
    }
    garnet_kernel<<<Bc, 32>>>(fi, dav, (float*)d_out);
}

// round 14
// speedup vs baseline: 1.0761x; 1.0115x over previous
#include <cuda_runtime.h>

// GarNet aggregation: out[b, s*64+n] = (sum_v w[v,s]) * (sum_v w[v,s]*fi[v,n]) / (128*128)
// with w = exp(-d_av^2).  B=4096, V=128, S=16, N=64.
//
// R14: one-warp CTAs, VCH=8, 4-STAGE cp.async pipeline with cp_wait<3>:
// 10.25KB/CTA -> ~20 CTAs/SM while keeping ~1500cyc latency slack.
// w computed in place over the d stage.
static constexpr int Bc = 4096;
static constexpr int Vc = 128;
static constexpr int Sc = 16;
static constexpr int Nc = 64;
static constexpr int VCH = 8;        // v per chunk
static constexpr int NCH = Vc / VCH; // 16 chunks
static constexpr int NST = 4;        // pipeline stages

// Smem (floats): fi 4 stages x (8*64) | d/w 4 stages x (8*16), w in place
static constexpr int OFF_FI = 0;                  // 4*512 floats
static constexpr int OFF_D  = NST * VCH * Nc;     // 2048; 4*128 floats
static constexpr int SBUF   = OFF_D + NST * VCH * Sc;   // 2560 floats = 10240 B

typedef unsigned long long u64;

__device__ __forceinline__ u64 bcast2(float x) {
    u64 r; unsigned xi = __float_as_uint(x);
    asm("mov.b64 %0, {%1, %1};" : "=l"(r) : "r"(xi));
    return r;
}
__device__ __forceinline__ void ffma2(u64 &c, u64 a, u64 b) {
    asm("fma.rn.f32x2 %0, %1, %2, %0;" : "+l"(c) : "l"(a), "l"(b));
}
__device__ __forceinline__ float lo32(u64 v) { return __uint_as_float((unsigned)(v & 0xffffffffull)); }
__device__ __forceinline__ float hi32(u64 v) { return __uint_as_float((unsigned)(v >> 32)); }

__device__ __forceinline__ void cp16(unsigned saddr, const void* gaddr) {
    asm volatile("cp.async.cg.shared.global [%0], [%1], 16;" :: "r"(saddr), "l"(gaddr));
}
__device__ __forceinline__ void cp_commit() {
    asm volatile("cp.async.commit_group;" ::: "memory");
}
template <int N>
__device__ __forceinline__ void cp_wait() {
    asm volatile("cp.async.wait_group %0;" :: "n"(N) : "memory");
}

__global__ __launch_bounds__(32)
void garnet_kernel(const float* __restrict__ fi,
                   const float* __restrict__ dav,
                   float* __restrict__ out) {
    __shared__ __align__(16) float s_buf[SBUF];
    __shared__ float s_wbar[Sc];

    const int lane = threadIdx.x & 31;
    const int ng   = lane & 15;   // n-group: owns n = ng*4 .. ng*4+3
    const int sh   = lane >> 4;   // s-half:  owns s = sh*8 .. sh*8+7
    const long b   = (long)blockIdx.x;

    unsigned sw = (unsigned)__cvta_generic_to_shared(s_buf);
    const float* fi_g = fi  + b * (long)(Vc * Nc);
    const float* d_g  = dav + b * (long)(Vc * Sc);

    // ---- issue chunk c into stage c%4: 4 fi cp16 + 1 d cp16 per lane --------
    auto issue = [&](int c) {
        int st = c & (NST - 1);
        unsigned fidst = sw + (OFF_FI + st * (VCH * Nc)) * 4 + lane * 16;
        const float* fisrc = fi_g + c * (VCH * Nc) + lane * 4;
        #pragma unroll
        for (int i = 0; i < 4; i++)
            cp16(fidst + i * 512, fisrc + i * 128);
        unsigned ddst = sw + (OFF_D + st * (VCH * Sc)) * 4 + lane * 16;
        const float* dsrc = d_g + c * (VCH * Sc) + lane * 4;
        cp16(ddst, dsrc);
        cp_commit();
    };

    u64 acc[16];   // acc[sp*4+j]: lo = s=sh*8+2sp, hi = s+1, n = ng*4+j
    #pragma unroll
    for (int i = 0; i < 16; i++) acc[i] = 0ull;
    float wb0 = 0.f, wb1 = 0.f, wb2 = 0.f, wb3 = 0.f;  // col partials, s=(lane&3)*4+k

    issue(0); issue(1); issue(2);

    #pragma unroll 4
    for (int c = 0; c < NCH; c++) {
        if (c + 3 < NCH)      { issue(c + 3); cp_wait<3>(); }
        else if (c + 2 < NCH) { cp_wait<2>(); }
        else if (c + 1 < NCH) { cp_wait<1>(); }
        else                  { cp_wait<0>(); }
        __syncwarp();

        const int st = c & (NST - 1);
        // ---- w = exp(-d^2), IN PLACE over the d stage (32 float4s) ---------
        float4* dwbuf = (float4*)(s_buf + OFF_D + st * (VCH * Sc));
        {
            float4 d4 = dwbuf[lane];
            float4 w4;
            w4.x = __expf(-d4.x * d4.x);
            w4.y = __expf(-d4.y * d4.y);
            w4.z = __expf(-d4.z * d4.z);
            w4.w = __expf(-d4.w * d4.w);
            dwbuf[lane] = w4;
            wb0 += w4.x; wb1 += w4.y; wb2 += w4.z; wb3 += w4.w;
        }
        __syncwarp();

        // ---- FFMA2 over the 8 v of this chunk (all smem) -------------------
        const float4* fibuf = (const float4*)(s_buf + OFF_FI + st * (VCH * Nc));
        const float*  wf    = s_buf + OFF_D + st * (VCH * Sc) + sh * 8;
        #pragma unroll
        for (int vv = 0; vv < VCH; vv++) {
            float4 f4 = fibuf[vv * (Nc / 4) + ng];
            const ulonglong2* wp = (const ulonglong2*)(wf + vv * Sc);
            ulonglong2 wA = wp[0], wB = wp[1];
            u64 w0 = wA.x, w1 = wA.y, w2 = wB.x, w3 = wB.y;
            u64 f0 = bcast2(f4.x), f1 = bcast2(f4.y);
            u64 f2 = bcast2(f4.z), f3 = bcast2(f4.w);
            ffma2(acc[ 0], w0, f0); ffma2(acc[ 1], w0, f1);
            ffma2(acc[ 2], w0, f2); ffma2(acc[ 3], w0, f3);
            ffma2(acc[ 4], w1, f0); ffma2(acc[ 5], w1, f1);
            ffma2(acc[ 6], w1, f2); ffma2(acc[ 7], w1, f3);
            ffma2(acc[ 8], w2, f0); ffma2(acc[ 9], w2, f1);
            ffma2(acc[10], w2, f2); ffma2(acc[11], w2, f3);
            ffma2(acc[12], w3, f0); ffma2(acc[13], w3, f1);
            ffma2(acc[14], w3, f2); ffma2(acc[15], w3, f3);
        }
        __syncwarp();   // stage is reused by cp.async four chunks later
    }

    // ---- wbar: reduce col partials over lanes of same class (lane&3) --------
    wb0 += __shfl_xor_sync(0xffffffffu, wb0, 16);
    wb0 += __shfl_xor_sync(0xffffffffu, wb0, 8);
    wb0 += __shfl_xor_sync(0xffffffffu, wb0, 4);
    wb1 += __shfl_xor_sync(0xffffffffu, wb1, 16);
    wb1 += __shfl_xor_sync(0xffffffffu, wb1, 8);
    wb1 += __shfl_xor_sync(0xffffffffu, wb1, 4);
    wb2 += __shfl_xor_sync(0xffffffffu, wb2, 16);
    wb2 += __shfl_xor_sync(0xffffffffu, wb2, 8);
    wb2 += __shfl_xor_sync(0xffffffffu, wb2, 4);
    wb3 += __shfl_xor_sync(0xffffffffu, wb3, 16);
    wb3 += __shfl_xor_sync(0xffffffffu, wb3, 8);
    wb3 += __shfl_xor_sync(0xffffffffu, wb3, 4);
    if (lane < 4) {
        s_wbar[lane * 4 + 0] = wb0;
        s_wbar[lane * 4 + 1] = wb1;
        s_wbar[lane * 4 + 2] = wb2;
        s_wbar[lane * 4 + 3] = wb3;
    }
    __syncwarp();

    // ---- epilogue: out = wbar * acc / (V*V) ---------------------------------
    const float inv = 1.0f / 16384.0f;
    float* obase = out + b * (long)(Sc * Nc) + ng * 4;
    #pragma unroll
    for (int sp = 0; sp < 4; sp++) {
        int s0 = sh * 8 + 2 * sp;
        float se = s_wbar[s0]     * inv;
        float so = s_wbar[s0 + 1] * inv;
        float4 oe, oo;
        oe.x = lo32(acc[sp * 4 + 0]) * se;
        oe.y = lo32(acc[sp * 4 + 1]) * se;
        oe.z = lo32(acc[sp * 4 + 2]) * se;
        oe.w = lo32(acc[sp * 4 + 3]) * se;
        oo.x = hi32(acc[sp * 4 + 0]) * so;
        oo.y = hi32(acc[sp * 4 + 1]) * so;
        oo.z = hi32(acc[sp * 4 + 2]) * so;
        oo.w = hi32(acc[sp * 4 + 3]) * so;
        *(float4*)(obase + s0 * Nc)       = oe;
        *(float4*)(obase + (s0 + 1) * Nc) = oo;
    }
}

extern "C" void kernel_launch(void* const* d_in, const int* in_sizes, int n_in,
                              void* d_out, int out_size) {
    const float* fi  = (const float*)d_in[0];
    const float* dav = (const float*)d_in[1];
    // Defensive: identify by element count (d_av has 4096*128*16 elems)
    if (n_in >= 2 && in_sizes[0] == Bc * Vc * Sc) {
        const float* tmp = fi; fi = dav; dav = tmp;
    }
    garnet_kernel<<<Bc, 32>>>(fi, dav, (float*)d_out);
}